// round 13
// baseline (speedup 1.0000x reference)
#include <cuda_runtime.h>
#include <cuda_fp16.h>

// ---------------- problem constants ----------------
#define NWIN   1024
#define NTOK   128
#define DIMC   192
#define NHEADS 6
#define HDIM   32
#define QKVC   576
#define CATC   384
#define MROWS  (NWIN*NTOK)
#define SCALE  0.17677669529663687f

// ---------------- device-global scratch ----------------
__device__ float  g_biasf[NHEADS * NTOK * NTOK];   // gathered rel-pos bias, 393KB (L2-resident)
__device__ float  g_pbw [64 * QKVC];               // (tiled sine pos) @ w_qkv_mutual (scaled)
__device__ __half g_x16 [MROWS * DIMC];
__device__ __half g_q16 [MROWS * QKVC];
__device__ __half g_m16 [MROWS * QKVC];
__device__ __half g_cat16[MROWS * CATC];
__device__ __half g_wq16[QKVC * DIMC];
__device__ __half g_wm16[QKVC * DIMC];
__device__ __half g_wp16[DIMC * CATC];

// ---------------- helpers ----------------
__device__ __forceinline__ unsigned pkh2(float a, float b) {
    __half2 h = __floats2half2_rn(a, b);
    return *reinterpret_cast<unsigned*>(&h);
}

#define MMAH(d, a, b) \
    asm volatile("mma.sync.aligned.m16n8k16.row.col.f32.f16.f16.f32 " \
        "{%0,%1,%2,%3}, {%4,%5,%6,%7}, {%8,%9}, {%0,%1,%2,%3};" \
        : "+f"((d)[0]), "+f"((d)[1]), "+f"((d)[2]), "+f"((d)[3]) \
        : "r"((a)[0]), "r"((a)[1]), "r"((a)[2]), "r"((a)[3]), "r"((b)[0]), "r"((b)[1]))

__device__ __forceinline__ void ldsm4(unsigned &r0, unsigned &r1, unsigned &r2, unsigned &r3,
                                      const __half* p) {
    unsigned addr = (unsigned)__cvta_generic_to_shared(p);
    asm volatile("ldmatrix.sync.aligned.m8n8.x4.shared.b16 {%0,%1,%2,%3},[%4];"
                 : "=r"(r0), "=r"(r1), "=r"(r2), "=r"(r3) : "r"(addr));
}
__device__ __forceinline__ void ldsm4t(unsigned &r0, unsigned &r1, unsigned &r2, unsigned &r3,
                                       const __half* p) {
    unsigned addr = (unsigned)__cvta_generic_to_shared(p);
    asm volatile("ldmatrix.sync.aligned.m8n8.x4.trans.shared.b16 {%0,%1,%2,%3},[%4];"
                 : "=r"(r0), "=r"(r1), "=r"(r2), "=r"(r3) : "r"(addr));
}
__device__ __forceinline__ void cpa16(void* s, const void* g) {
    unsigned sa = (unsigned)__cvta_generic_to_shared(s);
    asm volatile("cp.async.cg.shared.global [%0], [%1], 16;" :: "r"(sa), "l"(g));
}

// ---------------- preprocessing ----------------
__global__ void bias_gather(const int* __restrict__ relidx, const float* __restrict__ rpb) {
    int i = blockIdx.x * 256 + threadIdx.x;        // 98304
    int h = i >> 14, r = i & 16383;
    g_biasf[i] = rpb[relidx[r] * NHEADS + h];
}

__global__ void cvt_x_kernel(const float* __restrict__ x) {
    int idx = blockIdx.x * 256 + threadIdx.x;
    float4 xv = reinterpret_cast<const float4*>(x)[idx];
    uint2 o;
    o.x = pkh2(xv.x, xv.y); o.y = pkh2(xv.z, xv.w);
    reinterpret_cast<uint2*>(g_x16)[idx] = o;
}

__global__ void cvt_w_all(const float* __restrict__ wq, const float* __restrict__ wm,
                          const float* __restrict__ wp) {
    int idx = blockIdx.x * 256 + threadIdx.x;
    const float* w; __half* o; int K, N, nscale;
    if (idx < QKVC * DIMC) {
        w = wq; o = g_wq16; K = DIMC; N = QKVC; nscale = DIMC;
    } else if (idx < 2 * QKVC * DIMC) {
        idx -= QKVC * DIMC;
        w = wm; o = g_wm16; K = DIMC; N = QKVC; nscale = DIMC;
    } else {
        idx -= 2 * QKVC * DIMC;
        w = wp; o = g_wp16; K = CATC; N = DIMC; nscale = 0;
    }
    int n = idx / K, k = idx - n * K;
    float v = w[k * N + n];
    if (n < nscale) v *= SCALE;
    o[idx] = __float2half_rn(v);
}

// pbw[r][n] = sum_k posb[r][k] * wm[k][n] (q-cols scaled) — fp32 exact path
__global__ void pbw_kernel(const float* __restrict__ posb, const float* __restrict__ wm) {
    int i = blockIdx.x * 128 + threadIdx.x;        // 36864
    int r = i / QKVC, n = i - r * QKVC;
    float s = 0.0f;
    #pragma unroll 16
    for (int k = 0; k < DIMC; k++)
        s += posb[r * DIMC + k] * wm[k * QKVC + n];
    if (n < DIMC) s *= SCALE;
    g_pbw[i] = s;
}

// ---------------- fp16 GEMM, 4-stage cp.async, 1 sync/iter (round-11 verified tile) ----------------
#define BM 128
#define BN 96
#define BK 32
#define SSTR 40
#define GSA (BM * SSTR)
#define GSB (BN * SSTR)
#define GSTG (GSA + GSB)          // 8960 halfs / stage
#define GEMM_SMEM (4 * GSTG * (int)sizeof(__half))   // 71680 B

__device__ __forceinline__ void gemm_body(
    const __half* __restrict__ A, const __half* __restrict__ B,
    const float* __restrict__ bias, const float* __restrict__ rowAdd,
    float* __restrict__ C, __half* __restrict__ Ch,
    int K, int N, int mBase, int nBase, __half* dsm) {

    const int tid  = threadIdx.x;
    const int lane = tid & 31, warp = tid >> 5;
    const int wr   = warp >> 1, wc = warp & 1;
    const int aRowL = (lane & 7) + ((lane >> 3) & 1) * 8;
    const int aColL = (lane >> 4) * 8;
    const int bRowL = (lane & 7) + (lane >> 4) * 8;
    const int bColL = ((lane >> 3) & 1) * 8;

    float acc[2][6][4];
    #pragma unroll
    for (int mt = 0; mt < 2; mt++)
        #pragma unroll
        for (int nt = 0; nt < 6; nt++)
            #pragma unroll
            for (int i = 0; i < 4; i++) acc[mt][nt][i] = 0.0f;

    const int nk = K / BK;

    auto issue = [&](int it) {
        __half* sa = dsm + (it & 3) * GSTG;
        __half* sb = sa + GSA;
        const int k0 = it * BK;
        #pragma unroll
        for (int j = 0; j < 4; j++) {
            int i = tid + j * 256;
            if (i < 512) {
                const int r = i >> 2, c = i & 3;
                cpa16(&sa[r * SSTR + c * 8], &A[(size_t)(mBase + r) * K + k0 + c * 8]);
            } else if (i < 896) {
                i -= 512;
                const int r = i >> 2, c = i & 3;
                cpa16(&sb[r * SSTR + c * 8], &B[(size_t)(nBase + r) * K + k0 + c * 8]);
            }
        }
        asm volatile("cp.async.commit_group;");
    };

    issue(0); issue(1); issue(2);

    for (int it = 0; it < nk; it++) {
        if (it + 3 <= nk)      asm volatile("cp.async.wait_group 2;");
        else if (it + 2 == nk) asm volatile("cp.async.wait_group 1;");
        else                   asm volatile("cp.async.wait_group 0;");
        __syncthreads();
        if (it + 3 < nk) issue(it + 3);

        const __half* sa = dsm + (it & 3) * GSTG;
        const __half* sb = sa + GSA;
        #pragma unroll
        for (int ks = 0; ks < 2; ks++) {
            const int kk = ks * 16;
            unsigned a[2][4], bb[3][4];
            #pragma unroll
            for (int mt = 0; mt < 2; mt++)
                ldsm4(a[mt][0], a[mt][1], a[mt][2], a[mt][3],
                      &sa[(wr * 32 + mt * 16 + aRowL) * SSTR + kk + aColL]);
            #pragma unroll
            for (int np = 0; np < 3; np++)
                ldsm4(bb[np][0], bb[np][1], bb[np][2], bb[np][3],
                      &sb[(wc * 48 + np * 16 + bRowL) * SSTR + kk + bColL]);
            #pragma unroll
            for (int mt = 0; mt < 2; mt++)
                #pragma unroll
                for (int np = 0; np < 3; np++) {
                    MMAH(acc[mt][2 * np],     a[mt], bb[np]);
                    MMAH(acc[mt][2 * np + 1], a[mt], bb[np] + 2);
                }
        }
    }

    const int g = lane >> 2, tg = lane & 3;
    #pragma unroll
    for (int mt = 0; mt < 2; mt++)
        #pragma unroll
        for (int nt = 0; nt < 6; nt++) {
            const int row = mBase + wr * 32 + mt * 16 + g;
            const int col = nBase + wc * 48 + nt * 8 + tg * 2;
            float v0 = acc[mt][nt][0], v1 = acc[mt][nt][1];
            float v2 = acc[mt][nt][2], v3 = acc[mt][nt][3];
            if (rowAdd) {
                const float* r0 = &rowAdd[(size_t)(row & 63) * QKVC + col];
                const float* r1 = &rowAdd[(size_t)((row + 8) & 63) * QKVC + col];
                v0 += r0[0]; v1 += r0[1]; v2 += r1[0]; v3 += r1[1];
            }
            if (Ch) {
                *reinterpret_cast<unsigned*>(&Ch[(size_t)row * N + col]) = pkh2(v0, v1);
                *reinterpret_cast<unsigned*>(&Ch[(size_t)(row + 8) * N + col]) = pkh2(v2, v3);
            } else {
                const float b0 = bias[col], b1 = bias[col + 1];
                *reinterpret_cast<float2*>(&C[(size_t)row * N + col]) =
                    make_float2(v0 + b0, v1 + b1);
                *reinterpret_cast<float2*>(&C[(size_t)(row + 8) * N + col]) =
                    make_float2(v2 + b0, v3 + b1);
            }
        }
}

__global__ void __launch_bounds__(256, 3)
gemm_qkv_kernel() {
    extern __shared__ __align__(16) __half dsm[];
    const int z = blockIdx.z;
    gemm_body(g_x16, z ? g_wm16 : g_wq16,
              nullptr, z ? g_pbw : nullptr,
              nullptr, z ? g_m16 : g_q16,
              DIMC, QKVC, blockIdx.y * BM, blockIdx.x * BN, dsm);
}

__global__ void __launch_bounds__(256, 3)
gemm_out_kernel(const float* __restrict__ bias, float* __restrict__ C) {
    extern __shared__ __align__(16) __half dsm[];
    gemm_body(g_cat16, g_wp16, bias, nullptr, C, nullptr,
              CATC, DIMC, blockIdx.y * BM, blockIdx.x * BN, dsm);
}

// ---------------- streaming fp16 MMA attention (self + mutual fused) ----------------
#define SATT 40
#define ATT_SMEM (2 * NTOK * SATT * (int)sizeof(__half))   // 20480 B (K/V)

__global__ void __launch_bounds__(256, 3)
attn_mma(const float* __restrict__ mask) {
    const int h = blockIdx.x, b = blockIdx.y, z = blockIdx.z;
    const int tid = threadIdx.x, lane = tid & 31, w = tid >> 5;
    extern __shared__ __align__(16) __half sm[];
    __half *Ks = sm, *Vs = sm + NTOK * SATT;

    const __half* src = z ? g_m16 : g_q16;

    #pragma unroll
    for (int s = 0; s < 2; s++) {
        __half* d = sm + s * NTOK * SATT;
        const int off = (s + 1) * DIMC + h * HDIM;
        #pragma unroll
        for (int i = 0; i < 2; i++) {
            int idx = i * 256 + tid, row = idx >> 2, c = idx & 3;
            cpa16(&d[row * SATT + c * 8], &src[((size_t)b * NTOK + row) * QKVC + off + c * 8]);
        }
    }
    asm volatile("cp.async.commit_group;");

    const int g = lane >> 2, tg = lane & 3;
    int qbase, kb, nstrips, outCol0, orow_base;
    const float* scm;            // mask (always)
    const float* scb = nullptr;  // rel-pos bias (self branch only)
    if (z == 0) {
        qbase = w * 16; kb = 0; nstrips = 8; orow_base = qbase;
        scm = mask + ((size_t)(b & 63) * NTOK + qbase + g) * NTOK;
        scb = g_biasf + ((size_t)h * NTOK + qbase + g) * NTOK;
        outCol0 = DIMC + h * HDIM;
    } else {
        const int ob = w * 16;
        qbase = (w < 4) ? (64 + ob) : (ob - 64);
        kb = (w < 4) ? 0 : 64; nstrips = 4; orow_base = ob;
        const int mrow0 = (w < 4) ? ob : (ob - 64);
        scm = mask + ((size_t)(b & 63) * NTOK + mrow0 + g) * NTOK;
        outCol0 = h * HDIM;
    }

    const __half* qg = src + ((size_t)b * NTOK + qbase) * QKVC + h * HDIM;
    unsigned a[2][4];
    #pragma unroll
    for (int ks2 = 0; ks2 < 2; ks2++)
        #pragma unroll
        for (int r2 = 0; r2 < 2; r2++) {
            const size_t o0 = (size_t)(g + r2 * 8) * QKVC + ks2 * 16 + tg * 2;
            a[ks2][r2]     = *reinterpret_cast<const unsigned*>(&qg[o0]);
            a[ks2][2 + r2] = *reinterpret_cast<const unsigned*>(&qg[o0 + 8]);
        }

    asm volatile("cp.async.wait_group 0;");
    __syncthreads();

    const int bRowL = (lane & 7) + (lane >> 4) * 8, bColL = ((lane >> 3) & 1) * 8;
    const int vRowL = lane & 15,                    vColL = ((lane >> 4) & 1) * 8;

    float o[4][4];
    #pragma unroll
    for (int nt = 0; nt < 4; nt++)
        #pragma unroll
        for (int i = 0; i < 4; i++) o[nt][i] = 0.0f;
    float rs0 = 0.f, rs1 = 0.f;

    for (int st = 0; st < nstrips; st++) {
        const int krow = kb + st * 16;
        float S[2][4];
        #pragma unroll
        for (int nt = 0; nt < 2; nt++)
            #pragma unroll
            for (int i = 0; i < 4; i++) S[nt][i] = 0.0f;

        #pragma unroll
        for (int ks2 = 0; ks2 < 2; ks2++) {
            unsigned bk[4];
            ldsm4(bk[0], bk[1], bk[2], bk[3], &Ks[(krow + bRowL) * SATT + ks2 * 16 + bColL]);
            MMAH(S[0], a[ks2], bk);
            MMAH(S[1], a[ks2], bk + 2);
        }

        unsigned pk[4];
        #pragma unroll
        for (int nt = 0; nt < 2; nt++) {
            const int col = st * 16 + nt * 8 + tg * 2;
            float2 m0 = *reinterpret_cast<const float2*>(&scm[col]);
            float2 m1 = *reinterpret_cast<const float2*>(&scm[8 * NTOK + col]);
            if (scb) {
                float2 b0 = *reinterpret_cast<const float2*>(&scb[col]);
                float2 b1 = *reinterpret_cast<const float2*>(&scb[8 * NTOK + col]);
                m0.x += b0.x; m0.y += b0.y; m1.x += b1.x; m1.y += b1.y;
            }
            float e0 = __expf(S[nt][0] + m0.x), e1 = __expf(S[nt][1] + m0.y);
            float e2 = __expf(S[nt][2] + m1.x), e3 = __expf(S[nt][3] + m1.y);
            rs0 += e0 + e1; rs1 += e2 + e3;
            pk[2 * nt]     = pkh2(e0, e1);
            pk[2 * nt + 1] = pkh2(e2, e3);
        }

        unsigned vh[8];
        ldsm4t(vh[0], vh[1], vh[2], vh[3], &Vs[(krow + vRowL) * SATT + vColL]);
        ldsm4t(vh[4], vh[5], vh[6], vh[7], &Vs[(krow + vRowL) * SATT + 16 + vColL]);
        #pragma unroll
        for (int nt = 0; nt < 4; nt++)
            MMAH(o[nt], pk, vh + 2 * nt);
    }

    rs0 += __shfl_xor_sync(0xffffffff, rs0, 1); rs0 += __shfl_xor_sync(0xffffffff, rs0, 2);
    rs1 += __shfl_xor_sync(0xffffffff, rs1, 1); rs1 += __shfl_xor_sync(0xffffffff, rs1, 2);
    const float i0 = 1.0f / rs0, i1 = 1.0f / rs1;

    const size_t outRow0 = (size_t)b * NTOK + orow_base + g;
    #pragma unroll
    for (int nt = 0; nt < 4; nt++) {
        const int col = outCol0 + nt * 8 + tg * 2;
        *reinterpret_cast<unsigned*>(&g_cat16[outRow0 * CATC + col]) =
            pkh2(o[nt][0] * i0, o[nt][1] * i0);
        *reinterpret_cast<unsigned*>(&g_cat16[(outRow0 + 8) * CATC + col]) =
            pkh2(o[nt][2] * i1, o[nt][3] * i1);
    }
}

// ---------------- launch ----------------
extern "C" void kernel_launch(void* const* d_in, const int* in_sizes, int n_in,
                              void* d_out, int out_size) {
    const float* x      = (const float*)d_in[0];
    const float* mask   = (const float*)d_in[1];
    const float* w_qkv  = (const float*)d_in[2];
    const float* w_qkvm = (const float*)d_in[3];
    const float* w_proj = (const float*)d_in[4];
    const float* b_proj = (const float*)d_in[5];
    const float* rpb    = (const float*)d_in[6];
    const float* posb   = (const float*)d_in[7];
    const int*   relidx = (const int*)  d_in[8];
    float* out = (float*)d_out;

    cudaFuncSetAttribute(gemm_qkv_kernel, cudaFuncAttributeMaxDynamicSharedMemorySize, GEMM_SMEM);
    cudaFuncSetAttribute(gemm_out_kernel, cudaFuncAttributeMaxDynamicSharedMemorySize, GEMM_SMEM);
    cudaFuncSetAttribute(attn_mma,        cudaFuncAttributeMaxDynamicSharedMemorySize, ATT_SMEM);

    bias_gather<<<384, 256>>>(relidx, rpb);
    cvt_x_kernel<<<24576, 256>>>(x);
    cvt_w_all<<<(2 * QKVC * DIMC + DIMC * CATC) / 256, 256>>>(w_qkv, w_qkvm, w_proj);
    pbw_kernel<<<288, 128>>>(posb, w_qkvm);

    gemm_qkv_kernel<<<dim3(QKVC / BN, MROWS / BM, 2), 256, GEMM_SMEM>>>();

    attn_mma<<<dim3(NHEADS, NWIN, 2), 256, ATT_SMEM>>>(mask);

    gemm_out_kernel<<<dim3(DIMC / BN, MROWS / BM), 256, GEMM_SMEM>>>(b_proj, out);
}

// round 15
// speedup vs baseline: 1.2406x; 1.2406x over previous
#include <cuda_runtime.h>
#include <cuda_fp16.h>

// ---------------- problem constants ----------------
#define NWIN   1024
#define NTOK   128
#define DIMC   192
#define NHEADS 6
#define HDIM   32
#define QKVC   576
#define CATC   384
#define MROWS  (NWIN*NTOK)
#define SCALE  0.17677669529663687f

// ---------------- device-global scratch ----------------
__device__ float  g_bm  [NHEADS * 64 * NTOK * NTOK];
__device__ __half g_x16 [MROWS * DIMC];
__device__ __half g_xm16[MROWS * DIMC];
__device__ __half g_q16 [MROWS * QKVC];
__device__ __half g_m16 [MROWS * QKVC];
__device__ __half g_cat16[MROWS * CATC];
__device__ __half g_wq16[QKVC * DIMC];
__device__ __half g_wm16[QKVC * DIMC];
__device__ __half g_wp16[DIMC * CATC];

// ---------------- helpers ----------------
__device__ __forceinline__ unsigned pkh2(float a, float b) {
    __half2 h = __floats2half2_rn(a, b);
    return *reinterpret_cast<unsigned*>(&h);
}

#define MMAH(d, a, b) \
    asm volatile("mma.sync.aligned.m16n8k16.row.col.f32.f16.f16.f32 " \
        "{%0,%1,%2,%3}, {%4,%5,%6,%7}, {%8,%9}, {%0,%1,%2,%3};" \
        : "+f"((d)[0]), "+f"((d)[1]), "+f"((d)[2]), "+f"((d)[3]) \
        : "r"((a)[0]), "r"((a)[1]), "r"((a)[2]), "r"((a)[3]), "r"((b)[0]), "r"((b)[1]))

__device__ __forceinline__ void ldsm4(unsigned &r0, unsigned &r1, unsigned &r2, unsigned &r3,
                                      const __half* p) {
    unsigned addr = (unsigned)__cvta_generic_to_shared(p);
    asm volatile("ldmatrix.sync.aligned.m8n8.x4.shared.b16 {%0,%1,%2,%3},[%4];"
                 : "=r"(r0), "=r"(r1), "=r"(r2), "=r"(r3) : "r"(addr));
}
__device__ __forceinline__ void ldsm4t(unsigned &r0, unsigned &r1, unsigned &r2, unsigned &r3,
                                       const __half* p) {
    unsigned addr = (unsigned)__cvta_generic_to_shared(p);
    asm volatile("ldmatrix.sync.aligned.m8n8.x4.trans.shared.b16 {%0,%1,%2,%3},[%4];"
                 : "=r"(r0), "=r"(r1), "=r"(r2), "=r"(r3) : "r"(addr));
}
__device__ __forceinline__ void cpa16(void* s, const void* g) {
    unsigned sa = (unsigned)__cvta_generic_to_shared(s);
    asm volatile("cp.async.cg.shared.global [%0], [%1], 16;" :: "r"(sa), "l"(g));
}

// ---------------- preprocessing (round-11 verified) ----------------
__global__ void bm_kernel(const float* __restrict__ mask, const int* __restrict__ relidx,
                          const float* __restrict__ rpb) {
    int i = blockIdx.x * 256 + threadIdx.x;
    int hw = i >> 14, r = i & 16383;
    int h = hw / 64, w = hw - h * 64;
    g_bm[i] = rpb[relidx[r] * NHEADS + h] + mask[w * 16384 + r];
}

__global__ void cvt_x_kernel(const float* __restrict__ x, const float* __restrict__ posb) {
    int idx = blockIdx.x * 256 + threadIdx.x;
    float4 xv = reinterpret_cast<const float4*>(x)[idx];
    int m = idx / 48, c4 = idx - m * 48;
    float4 pv = reinterpret_cast<const float4*>(posb)[(m & 63) * 48 + c4];
    uint2 o;
    o.x = pkh2(xv.x, xv.y); o.y = pkh2(xv.z, xv.w);
    reinterpret_cast<uint2*>(g_x16)[idx] = o;
    o.x = pkh2(xv.x + pv.x, xv.y + pv.y); o.y = pkh2(xv.z + pv.z, xv.w + pv.w);
    reinterpret_cast<uint2*>(g_xm16)[idx] = o;
}

__global__ void cvt_w_all(const float* __restrict__ wq, const float* __restrict__ wm,
                          const float* __restrict__ wp) {
    int idx = blockIdx.x * 256 + threadIdx.x;
    const float* w; __half* o; int K, N, nscale;
    if (idx < QKVC * DIMC) {
        w = wq; o = g_wq16; K = DIMC; N = QKVC; nscale = DIMC;
    } else if (idx < 2 * QKVC * DIMC) {
        idx -= QKVC * DIMC;
        w = wm; o = g_wm16; K = DIMC; N = QKVC; nscale = DIMC;
    } else {
        idx -= 2 * QKVC * DIMC;
        w = wp; o = g_wp16; K = CATC; N = DIMC; nscale = 0;
    }
    int n = idx / K, k = idx - n * K;
    float v = w[k * N + n];
    if (n < nscale) v *= SCALE;
    o[idx] = __float2half_rn(v);
}

// ---------------- fp16 GEMM: BK=64, 2-stage double buffer, 1 sync/iter ----------------
#define BM 128
#define BN 96
#define BK 64
#define SSTR 72
#define GSA (BM * SSTR)           // 9216 halfs
#define GSB (BN * SSTR)           // 6912 halfs
#define GSTG (GSA + GSB)          // 16128 halfs / stage
#define GEMM_SMEM (2 * GSTG * (int)sizeof(__half))   // 64512 B -> occ 3

__device__ __forceinline__ void gemm_body(
    const __half* __restrict__ A, const __half* __restrict__ B,
    const float* __restrict__ bias, float* __restrict__ C, __half* __restrict__ Ch,
    int K, int N, int mBase, int nBase, __half* dsm) {

    const int tid  = threadIdx.x;
    const int lane = tid & 31, warp = tid >> 5;
    const int wr   = warp >> 1, wc = warp & 1;
    const int aRowL = (lane & 7) + ((lane >> 3) & 1) * 8;
    const int aColL = (lane >> 4) * 8;
    const int bRowL = (lane & 7) + (lane >> 4) * 8;
    const int bColL = ((lane >> 3) & 1) * 8;

    float acc[2][6][4];
    #pragma unroll
    for (int mt = 0; mt < 2; mt++)
        #pragma unroll
        for (int nt = 0; nt < 6; nt++)
            #pragma unroll
            for (int i = 0; i < 4; i++) acc[mt][nt][i] = 0.0f;

    const int nk = K / BK;

    // per-chunk load: A 128x64 (1024 x16B) + B 96x64 (768 x16B) = 1792 -> 7/thread
    auto issue = [&](int it) {
        __half* sa = dsm + (it & 1) * GSTG;
        __half* sb = sa + GSA;
        const int k0 = it * BK;
        #pragma unroll
        for (int j = 0; j < 7; j++) {
            int i = tid + j * 256;
            if (i < 1024) {
                const int r = i >> 3, c = i & 7;
                cpa16(&sa[r * SSTR + c * 8], &A[(size_t)(mBase + r) * K + k0 + c * 8]);
            } else {
                i -= 1024;
                const int r = i >> 3, c = i & 7;
                cpa16(&sb[r * SSTR + c * 8], &B[(size_t)(nBase + r) * K + k0 + c * 8]);
            }
        }
        asm volatile("cp.async.commit_group;");
    };

    issue(0);

    for (int it = 0; it < nk; it++) {
        asm volatile("cp.async.wait_group 0;");
        __syncthreads();
        // Safe: stage (it+1)&1 was consumed in iteration it-1, retired by the sync above.
        if (it + 1 < nk) issue(it + 1);

        const __half* sa = dsm + (it & 1) * GSTG;
        const __half* sb = sa + GSA;
        #pragma unroll
        for (int ks = 0; ks < 4; ks++) {
            const int kk = ks * 16;
            unsigned a[2][4], bb[3][4];
            #pragma unroll
            for (int mt = 0; mt < 2; mt++)
                ldsm4(a[mt][0], a[mt][1], a[mt][2], a[mt][3],
                      &sa[(wr * 32 + mt * 16 + aRowL) * SSTR + kk + aColL]);
            #pragma unroll
            for (int np = 0; np < 3; np++)
                ldsm4(bb[np][0], bb[np][1], bb[np][2], bb[np][3],
                      &sb[(wc * 48 + np * 16 + bRowL) * SSTR + kk + bColL]);
            #pragma unroll
            for (int mt = 0; mt < 2; mt++)
                #pragma unroll
                for (int np = 0; np < 3; np++) {
                    MMAH(acc[mt][2 * np],     a[mt], bb[np]);
                    MMAH(acc[mt][2 * np + 1], a[mt], bb[np] + 2);
                }
        }
    }

    const int g = lane >> 2, tg = lane & 3;
    #pragma unroll
    for (int mt = 0; mt < 2; mt++)
        #pragma unroll
        for (int nt = 0; nt < 6; nt++) {
            const int row = mBase + wr * 32 + mt * 16 + g;
            const int col = nBase + wc * 48 + nt * 8 + tg * 2;
            if (Ch) {
                *reinterpret_cast<unsigned*>(&Ch[(size_t)row * N + col]) =
                    pkh2(acc[mt][nt][0], acc[mt][nt][1]);
                *reinterpret_cast<unsigned*>(&Ch[(size_t)(row + 8) * N + col]) =
                    pkh2(acc[mt][nt][2], acc[mt][nt][3]);
            } else {
                const float b0 = bias[col], b1 = bias[col + 1];
                *reinterpret_cast<float2*>(&C[(size_t)row * N + col]) =
                    make_float2(acc[mt][nt][0] + b0, acc[mt][nt][1] + b1);
                *reinterpret_cast<float2*>(&C[(size_t)(row + 8) * N + col]) =
                    make_float2(acc[mt][nt][2] + b0, acc[mt][nt][3] + b1);
            }
        }
}

__global__ void __launch_bounds__(256, 3)
gemm_qkv_kernel() {
    extern __shared__ __align__(16) __half dsm[];
    const int z = blockIdx.z;
    gemm_body(z ? g_xm16 : g_x16, z ? g_wm16 : g_wq16,
              nullptr, nullptr, z ? g_m16 : g_q16,
              DIMC, QKVC, blockIdx.y * BM, blockIdx.x * BN, dsm);
}

__global__ void __launch_bounds__(256, 3)
gemm_out_kernel(const float* __restrict__ bias, float* __restrict__ C) {
    extern __shared__ __align__(16) __half dsm[];
    gemm_body(g_cat16, g_wp16, bias, C, nullptr,
              CATC, DIMC, blockIdx.y * BM, blockIdx.x * BN, dsm);
}

// ---------------- streaming fp16 MMA attention (round-11 verified) ----------------
#define SATT 40
#define ATT_SMEM (2 * NTOK * SATT * (int)sizeof(__half))   // 20480 B (K/V)

__global__ void __launch_bounds__(256, 3)
attn_mma(const float* __restrict__ mask) {
    const int h = blockIdx.x, b = blockIdx.y, z = blockIdx.z;
    const int tid = threadIdx.x, lane = tid & 31, w = tid >> 5;
    extern __shared__ __align__(16) __half sm[];
    __half *Ks = sm, *Vs = sm + NTOK * SATT;

    const __half* src = z ? g_m16 : g_q16;

    #pragma unroll
    for (int s = 0; s < 2; s++) {
        __half* d = sm + s * NTOK * SATT;
        const int off = (s + 1) * DIMC + h * HDIM;
        #pragma unroll
        for (int i = 0; i < 2; i++) {
            int idx = i * 256 + tid, row = idx >> 2, c = idx & 3;
            cpa16(&d[row * SATT + c * 8], &src[((size_t)b * NTOK + row) * QKVC + off + c * 8]);
        }
    }
    asm volatile("cp.async.commit_group;");

    const int g = lane >> 2, tg = lane & 3;
    int qbase, kb, nstrips, outCol0, orow_base;
    const float* sc;
    if (z == 0) {
        qbase = w * 16; kb = 0; nstrips = 8; orow_base = qbase;
        sc = g_bm + ((size_t)(h * 64 + (b & 63)) * NTOK + qbase + g) * NTOK;
        outCol0 = DIMC + h * HDIM;
    } else {
        const int ob = w * 16;
        qbase = (w < 4) ? (64 + ob) : (ob - 64);
        kb = (w < 4) ? 0 : 64; nstrips = 4; orow_base = ob;
        const int mrow0 = (w < 4) ? ob : (ob - 64);
        sc = mask + ((size_t)(b & 63) * NTOK + mrow0 + g) * NTOK;
        outCol0 = h * HDIM;
    }

    const __half* qg = src + ((size_t)b * NTOK + qbase) * QKVC + h * HDIM;
    unsigned a[2][4];
    #pragma unroll
    for (int ks2 = 0; ks2 < 2; ks2++)
        #pragma unroll
        for (int r2 = 0; r2 < 2; r2++) {
            const size_t o0 = (size_t)(g + r2 * 8) * QKVC + ks2 * 16 + tg * 2;
            a[ks2][r2]     = *reinterpret_cast<const unsigned*>(&qg[o0]);
            a[ks2][2 + r2] = *reinterpret_cast<const unsigned*>(&qg[o0 + 8]);
        }

    asm volatile("cp.async.wait_group 0;");
    __syncthreads();

    const int bRowL = (lane & 7) + (lane >> 4) * 8, bColL = ((lane >> 3) & 1) * 8;
    const int vRowL = lane & 15,                    vColL = ((lane >> 4) & 1) * 8;

    float o[4][4];
    #pragma unroll
    for (int nt = 0; nt < 4; nt++)
        #pragma unroll
        for (int i = 0; i < 4; i++) o[nt][i] = 0.0f;
    float rs0 = 0.f, rs1 = 0.f;

    for (int st = 0; st < nstrips; st++) {
        const int krow = kb + st * 16;
        float S[2][4];
        #pragma unroll
        for (int nt = 0; nt < 2; nt++)
            #pragma unroll
            for (int i = 0; i < 4; i++) S[nt][i] = 0.0f;

        #pragma unroll
        for (int ks2 = 0; ks2 < 2; ks2++) {
            unsigned bk[4];
            ldsm4(bk[0], bk[1], bk[2], bk[3], &Ks[(krow + bRowL) * SATT + ks2 * 16 + bColL]);
            MMAH(S[0], a[ks2], bk);
            MMAH(S[1], a[ks2], bk + 2);
        }

        unsigned pk[4];
        #pragma unroll
        for (int nt = 0; nt < 2; nt++) {
            const int col = st * 16 + nt * 8 + tg * 2;
            float2 m0 = *reinterpret_cast<const float2*>(&sc[col]);
            float2 m1 = *reinterpret_cast<const float2*>(&sc[8 * NTOK + col]);
            float e0 = __expf(S[nt][0] + m0.x), e1 = __expf(S[nt][1] + m0.y);
            float e2 = __expf(S[nt][2] + m1.x), e3 = __expf(S[nt][3] + m1.y);
            rs0 += e0 + e1; rs1 += e2 + e3;
            pk[2 * nt]     = pkh2(e0, e1);
            pk[2 * nt + 1] = pkh2(e2, e3);
        }

        unsigned vh[8];
        ldsm4t(vh[0], vh[1], vh[2], vh[3], &Vs[(krow + vRowL) * SATT + vColL]);
        ldsm4t(vh[4], vh[5], vh[6], vh[7], &Vs[(krow + vRowL) * SATT + 16 + vColL]);
        #pragma unroll
        for (int nt = 0; nt < 4; nt++)
            MMAH(o[nt], pk, vh + 2 * nt);
    }

    rs0 += __shfl_xor_sync(0xffffffff, rs0, 1); rs0 += __shfl_xor_sync(0xffffffff, rs0, 2);
    rs1 += __shfl_xor_sync(0xffffffff, rs1, 1); rs1 += __shfl_xor_sync(0xffffffff, rs1, 2);
    const float i0 = 1.0f / rs0, i1 = 1.0f / rs1;

    const size_t outRow0 = (size_t)b * NTOK + orow_base + g;
    #pragma unroll
    for (int nt = 0; nt < 4; nt++) {
        const int col = outCol0 + nt * 8 + tg * 2;
        *reinterpret_cast<unsigned*>(&g_cat16[outRow0 * CATC + col]) =
            pkh2(o[nt][0] * i0, o[nt][1] * i0);
        *reinterpret_cast<unsigned*>(&g_cat16[(outRow0 + 8) * CATC + col]) =
            pkh2(o[nt][2] * i1, o[nt][3] * i1);
    }
}

// ---------------- launch ----------------
extern "C" void kernel_launch(void* const* d_in, const int* in_sizes, int n_in,
                              void* d_out, int out_size) {
    const float* x      = (const float*)d_in[0];
    const float* mask   = (const float*)d_in[1];
    const float* w_qkv  = (const float*)d_in[2];
    const float* w_qkvm = (const float*)d_in[3];
    const float* w_proj = (const float*)d_in[4];
    const float* b_proj = (const float*)d_in[5];
    const float* rpb    = (const float*)d_in[6];
    const float* posb   = (const float*)d_in[7];
    const int*   relidx = (const int*)  d_in[8];
    float* out = (float*)d_out;

    cudaFuncSetAttribute(gemm_qkv_kernel, cudaFuncAttributeMaxDynamicSharedMemorySize, GEMM_SMEM);
    cudaFuncSetAttribute(gemm_out_kernel, cudaFuncAttributeMaxDynamicSharedMemorySize, GEMM_SMEM);
    cudaFuncSetAttribute(attn_mma,        cudaFuncAttributeMaxDynamicSharedMemorySize, ATT_SMEM);

    bm_kernel<<<24576, 256>>>(mask, relidx, rpb);
    cvt_x_kernel<<<24576, 256>>>(x, posb);
    cvt_w_all<<<(2 * QKVC * DIMC + DIMC * CATC) / 256, 256>>>(w_qkv, w_qkvm, w_proj);

    gemm_qkv_kernel<<<dim3(QKVC / BN, MROWS / BM, 2), 256, GEMM_SMEM>>>();

    attn_mma<<<dim3(NHEADS, NWIN, 2), 256, ATT_SMEM>>>(mask);

    gemm_out_kernel<<<dim3(DIMC / BN, MROWS / BM), 256, GEMM_SMEM>>>(b_proj, out);
}

// round 16
// speedup vs baseline: 1.2513x; 1.0086x over previous
#include <cuda_runtime.h>
#include <cuda_fp16.h>

// ---------------- problem constants ----------------
#define NWIN   1024
#define NTOK   128
#define DIMC   192
#define NHEADS 6
#define HDIM   32
#define QKVC   576
#define CATC   384
#define MROWS  (NWIN*NTOK)
#define SCALE  0.17677669529663687f

// ---------------- device-global scratch ----------------
__device__ float  g_bm  [NHEADS * 64 * NTOK * NTOK];
__device__ __half g_x16 [MROWS * DIMC];
__device__ __half g_xm16[MROWS * DIMC];
__device__ __half g_q16 [MROWS * QKVC];
__device__ __half g_m16 [MROWS * QKVC];
__device__ __half g_cat16[MROWS * CATC];
__device__ __half g_wq16[QKVC * DIMC];
__device__ __half g_wm16[QKVC * DIMC];
__device__ __half g_wp16[DIMC * CATC];

// ---------------- helpers ----------------
__device__ __forceinline__ unsigned pkh2(float a, float b) {
    __half2 h = __floats2half2_rn(a, b);
    return *reinterpret_cast<unsigned*>(&h);
}

#define MMAH(d, a, b) \
    asm volatile("mma.sync.aligned.m16n8k16.row.col.f32.f16.f16.f32 " \
        "{%0,%1,%2,%3}, {%4,%5,%6,%7}, {%8,%9}, {%0,%1,%2,%3};" \
        : "+f"((d)[0]), "+f"((d)[1]), "+f"((d)[2]), "+f"((d)[3]) \
        : "r"((a)[0]), "r"((a)[1]), "r"((a)[2]), "r"((a)[3]), "r"((b)[0]), "r"((b)[1]))

__device__ __forceinline__ void ldsm4(unsigned &r0, unsigned &r1, unsigned &r2, unsigned &r3,
                                      const __half* p) {
    unsigned addr = (unsigned)__cvta_generic_to_shared(p);
    asm volatile("ldmatrix.sync.aligned.m8n8.x4.shared.b16 {%0,%1,%2,%3},[%4];"
                 : "=r"(r0), "=r"(r1), "=r"(r2), "=r"(r3) : "r"(addr));
}
__device__ __forceinline__ void ldsm4t(unsigned &r0, unsigned &r1, unsigned &r2, unsigned &r3,
                                       const __half* p) {
    unsigned addr = (unsigned)__cvta_generic_to_shared(p);
    asm volatile("ldmatrix.sync.aligned.m8n8.x4.trans.shared.b16 {%0,%1,%2,%3},[%4];"
                 : "=r"(r0), "=r"(r1), "=r"(r2), "=r"(r3) : "r"(addr));
}
__device__ __forceinline__ void cpa16(void* s, const void* g) {
    unsigned sa = (unsigned)__cvta_generic_to_shared(s);
    asm volatile("cp.async.cg.shared.global [%0], [%1], 16;" :: "r"(sa), "l"(g));
}

// ---------------- merged preprocessing (bm + cvt_x + cvt_w in one launch) ----------------
#define NBM   (NHEADS * 64 * NTOK * NTOK)        // 6,291,456
#define NCX   ((MROWS * DIMC) / 4)               // 6,291,456 float4s
#define NCW   (2 * QKVC * DIMC + DIMC * CATC)    // 294,912
#define NPRE  (NBM + NCX + NCW)

__global__ void preproc_all(const float* __restrict__ mask, const int* __restrict__ relidx,
                            const float* __restrict__ rpb, const float* __restrict__ x,
                            const float* __restrict__ posb, const float* __restrict__ wq,
                            const float* __restrict__ wm, const float* __restrict__ wp) {
    int idx = blockIdx.x * 256 + threadIdx.x;
    if (idx < NBM) {
        // g_bm[h][w][t][k] = rpb[relidx[t,k]][h] + mask[w][t][k]
        int hw = idx >> 14, r = idx & 16383;
        int h = hw / 64, w = hw - h * 64;
        g_bm[idx] = rpb[relidx[r] * NHEADS + h] + mask[w * 16384 + r];
    } else if (idx < NBM + NCX) {
        int i = idx - NBM;
        float4 xv = reinterpret_cast<const float4*>(x)[i];
        int m = i / 48, c4 = i - m * 48;
        float4 pv = reinterpret_cast<const float4*>(posb)[(m & 63) * 48 + c4];
        uint2 o;
        o.x = pkh2(xv.x, xv.y); o.y = pkh2(xv.z, xv.w);
        reinterpret_cast<uint2*>(g_x16)[i] = o;
        o.x = pkh2(xv.x + pv.x, xv.y + pv.y); o.y = pkh2(xv.z + pv.z, xv.w + pv.w);
        reinterpret_cast<uint2*>(g_xm16)[i] = o;
    } else if (idx < NPRE) {
        int i = idx - NBM - NCX;
        const float* w; __half* o; int K, N, nscale;
        if (i < QKVC * DIMC) {
            w = wq; o = g_wq16; K = DIMC; N = QKVC; nscale = DIMC;
        } else if (i < 2 * QKVC * DIMC) {
            i -= QKVC * DIMC;
            w = wm; o = g_wm16; K = DIMC; N = QKVC; nscale = DIMC;
        } else {
            i -= 2 * QKVC * DIMC;
            w = wp; o = g_wp16; K = CATC; N = DIMC; nscale = 0;
        }
        int n = i / K, k = i - n * K;
        float v = w[k * N + n];
        if (n < nscale) v *= SCALE;
        o[i] = __float2half_rn(v);
    }
}

// ---------------- fp16 GEMM: BK=64, 2-stage double buffer, 1 sync/iter (r15 verified) ----------------
#define BM 128
#define BN 96
#define BK 64
#define SSTR 72
#define GSA (BM * SSTR)
#define GSB (BN * SSTR)
#define GSTG (GSA + GSB)
#define GEMM_SMEM (2 * GSTG * (int)sizeof(__half))   // 64512 B -> occ 3

__device__ __forceinline__ void gemm_body(
    const __half* __restrict__ A, const __half* __restrict__ B,
    const float* __restrict__ bias, float* __restrict__ C, __half* __restrict__ Ch,
    int K, int N, int mBase, int nBase, __half* dsm) {

    const int tid  = threadIdx.x;
    const int lane = tid & 31, warp = tid >> 5;
    const int wr   = warp >> 1, wc = warp & 1;
    const int aRowL = (lane & 7) + ((lane >> 3) & 1) * 8;
    const int aColL = (lane >> 4) * 8;
    const int bRowL = (lane & 7) + (lane >> 4) * 8;
    const int bColL = ((lane >> 3) & 1) * 8;

    float acc[2][6][4];
    #pragma unroll
    for (int mt = 0; mt < 2; mt++)
        #pragma unroll
        for (int nt = 0; nt < 6; nt++)
            #pragma unroll
            for (int i = 0; i < 4; i++) acc[mt][nt][i] = 0.0f;

    const int nk = K / BK;

    auto issue = [&](int it) {
        __half* sa = dsm + (it & 1) * GSTG;
        __half* sb = sa + GSA;
        const int k0 = it * BK;
        #pragma unroll
        for (int j = 0; j < 7; j++) {
            int i = tid + j * 256;
            if (i < 1024) {
                const int r = i >> 3, c = i & 7;
                cpa16(&sa[r * SSTR + c * 8], &A[(size_t)(mBase + r) * K + k0 + c * 8]);
            } else {
                i -= 1024;
                const int r = i >> 3, c = i & 7;
                cpa16(&sb[r * SSTR + c * 8], &B[(size_t)(nBase + r) * K + k0 + c * 8]);
            }
        }
        asm volatile("cp.async.commit_group;");
    };

    issue(0);

    for (int it = 0; it < nk; it++) {
        asm volatile("cp.async.wait_group 0;");
        __syncthreads();
        // Safe: stage (it+1)&1 was consumed in iteration it-1, retired by the sync above.
        if (it + 1 < nk) issue(it + 1);

        const __half* sa = dsm + (it & 1) * GSTG;
        const __half* sb = sa + GSA;
        #pragma unroll
        for (int ks = 0; ks < 4; ks++) {
            const int kk = ks * 16;
            unsigned a[2][4], bb[3][4];
            #pragma unroll
            for (int mt = 0; mt < 2; mt++)
                ldsm4(a[mt][0], a[mt][1], a[mt][2], a[mt][3],
                      &sa[(wr * 32 + mt * 16 + aRowL) * SSTR + kk + aColL]);
            #pragma unroll
            for (int np = 0; np < 3; np++)
                ldsm4(bb[np][0], bb[np][1], bb[np][2], bb[np][3],
                      &sb[(wc * 48 + np * 16 + bRowL) * SSTR + kk + bColL]);
            #pragma unroll
            for (int mt = 0; mt < 2; mt++)
                #pragma unroll
                for (int np = 0; np < 3; np++) {
                    MMAH(acc[mt][2 * np],     a[mt], bb[np]);
                    MMAH(acc[mt][2 * np + 1], a[mt], bb[np] + 2);
                }
        }
    }

    const int g = lane >> 2, tg = lane & 3;
    #pragma unroll
    for (int mt = 0; mt < 2; mt++)
        #pragma unroll
        for (int nt = 0; nt < 6; nt++) {
            const int row = mBase + wr * 32 + mt * 16 + g;
            const int col = nBase + wc * 48 + nt * 8 + tg * 2;
            if (Ch) {
                *reinterpret_cast<unsigned*>(&Ch[(size_t)row * N + col]) =
                    pkh2(acc[mt][nt][0], acc[mt][nt][1]);
                *reinterpret_cast<unsigned*>(&Ch[(size_t)(row + 8) * N + col]) =
                    pkh2(acc[mt][nt][2], acc[mt][nt][3]);
            } else {
                const float b0 = bias[col], b1 = bias[col + 1];
                *reinterpret_cast<float2*>(&C[(size_t)row * N + col]) =
                    make_float2(acc[mt][nt][0] + b0, acc[mt][nt][1] + b1);
                *reinterpret_cast<float2*>(&C[(size_t)(row + 8) * N + col]) =
                    make_float2(acc[mt][nt][2] + b0, acc[mt][nt][3] + b1);
            }
        }
}

__global__ void __launch_bounds__(256, 3)
gemm_qkv_kernel() {
    extern __shared__ __align__(16) __half dsm[];
    const int z = blockIdx.z;
    gemm_body(z ? g_xm16 : g_x16, z ? g_wm16 : g_wq16,
              nullptr, nullptr, z ? g_m16 : g_q16,
              DIMC, QKVC, blockIdx.y * BM, blockIdx.x * BN, dsm);
}

__global__ void __launch_bounds__(256, 3)
gemm_out_kernel(const float* __restrict__ bias, float* __restrict__ C) {
    extern __shared__ __align__(16) __half dsm[];
    gemm_body(g_cat16, g_wp16, bias, C, nullptr,
              CATC, DIMC, blockIdx.y * BM, blockIdx.x * BN, dsm);
}

// ---------------- streaming fp16 MMA attention (r11/r15 verified) ----------------
#define SATT 40
#define ATT_SMEM (2 * NTOK * SATT * (int)sizeof(__half))   // 20480 B (K/V)

__global__ void __launch_bounds__(256, 3)
attn_mma(const float* __restrict__ mask) {
    const int h = blockIdx.x, b = blockIdx.y, z = blockIdx.z;
    const int tid = threadIdx.x, lane = tid & 31, w = tid >> 5;
    extern __shared__ __align__(16) __half sm[];
    __half *Ks = sm, *Vs = sm + NTOK * SATT;

    const __half* src = z ? g_m16 : g_q16;

    #pragma unroll
    for (int s = 0; s < 2; s++) {
        __half* d = sm + s * NTOK * SATT;
        const int off = (s + 1) * DIMC + h * HDIM;
        #pragma unroll
        for (int i = 0; i < 2; i++) {
            int idx = i * 256 + tid, row = idx >> 2, c = idx & 3;
            cpa16(&d[row * SATT + c * 8], &src[((size_t)b * NTOK + row) * QKVC + off + c * 8]);
        }
    }
    asm volatile("cp.async.commit_group;");

    const int g = lane >> 2, tg = lane & 3;
    int qbase, kb, nstrips, outCol0, orow_base;
    const float* sc;
    if (z == 0) {
        qbase = w * 16; kb = 0; nstrips = 8; orow_base = qbase;
        sc = g_bm + ((size_t)(h * 64 + (b & 63)) * NTOK + qbase + g) * NTOK;
        outCol0 = DIMC + h * HDIM;
    } else {
        const int ob = w * 16;
        qbase = (w < 4) ? (64 + ob) : (ob - 64);
        kb = (w < 4) ? 0 : 64; nstrips = 4; orow_base = ob;
        const int mrow0 = (w < 4) ? ob : (ob - 64);
        sc = mask + ((size_t)(b & 63) * NTOK + mrow0 + g) * NTOK;
        outCol0 = h * HDIM;
    }

    const __half* qg = src + ((size_t)b * NTOK + qbase) * QKVC + h * HDIM;
    unsigned a[2][4];
    #pragma unroll
    for (int ks2 = 0; ks2 < 2; ks2++)
        #pragma unroll
        for (int r2 = 0; r2 < 2; r2++) {
            const size_t o0 = (size_t)(g + r2 * 8) * QKVC + ks2 * 16 + tg * 2;
            a[ks2][r2]     = *reinterpret_cast<const unsigned*>(&qg[o0]);
            a[ks2][2 + r2] = *reinterpret_cast<const unsigned*>(&qg[o0 + 8]);
        }

    asm volatile("cp.async.wait_group 0;");
    __syncthreads();

    const int bRowL = (lane & 7) + (lane >> 4) * 8, bColL = ((lane >> 3) & 1) * 8;
    const int vRowL = lane & 15,                    vColL = ((lane >> 4) & 1) * 8;

    float o[4][4];
    #pragma unroll
    for (int nt = 0; nt < 4; nt++)
        #pragma unroll
        for (int i = 0; i < 4; i++) o[nt][i] = 0.0f;
    float rs0 = 0.f, rs1 = 0.f;

    for (int st = 0; st < nstrips; st++) {
        const int krow = kb + st * 16;
        float S[2][4];
        #pragma unroll
        for (int nt = 0; nt < 2; nt++)
            #pragma unroll
            for (int i = 0; i < 4; i++) S[nt][i] = 0.0f;

        #pragma unroll
        for (int ks2 = 0; ks2 < 2; ks2++) {
            unsigned bk[4];
            ldsm4(bk[0], bk[1], bk[2], bk[3], &Ks[(krow + bRowL) * SATT + ks2 * 16 + bColL]);
            MMAH(S[0], a[ks2], bk);
            MMAH(S[1], a[ks2], bk + 2);
        }

        unsigned pk[4];
        #pragma unroll
        for (int nt = 0; nt < 2; nt++) {
            const int col = st * 16 + nt * 8 + tg * 2;
            float2 m0 = *reinterpret_cast<const float2*>(&sc[col]);
            float2 m1 = *reinterpret_cast<const float2*>(&sc[8 * NTOK + col]);
            float e0 = __expf(S[nt][0] + m0.x), e1 = __expf(S[nt][1] + m0.y);
            float e2 = __expf(S[nt][2] + m1.x), e3 = __expf(S[nt][3] + m1.y);
            rs0 += e0 + e1; rs1 += e2 + e3;
            pk[2 * nt]     = pkh2(e0, e1);
            pk[2 * nt + 1] = pkh2(e2, e3);
        }

        unsigned vh[8];
        ldsm4t(vh[0], vh[1], vh[2], vh[3], &Vs[(krow + vRowL) * SATT + vColL]);
        ldsm4t(vh[4], vh[5], vh[6], vh[7], &Vs[(krow + vRowL) * SATT + 16 + vColL]);
        #pragma unroll
        for (int nt = 0; nt < 4; nt++)
            MMAH(o[nt], pk, vh + 2 * nt);
    }

    rs0 += __shfl_xor_sync(0xffffffff, rs0, 1); rs0 += __shfl_xor_sync(0xffffffff, rs0, 2);
    rs1 += __shfl_xor_sync(0xffffffff, rs1, 1); rs1 += __shfl_xor_sync(0xffffffff, rs1, 2);
    const float i0 = 1.0f / rs0, i1 = 1.0f / rs1;

    const size_t outRow0 = (size_t)b * NTOK + orow_base + g;
    #pragma unroll
    for (int nt = 0; nt < 4; nt++) {
        const int col = outCol0 + nt * 8 + tg * 2;
        *reinterpret_cast<unsigned*>(&g_cat16[outRow0 * CATC + col]) =
            pkh2(o[nt][0] * i0, o[nt][1] * i0);
        *reinterpret_cast<unsigned*>(&g_cat16[(outRow0 + 8) * CATC + col]) =
            pkh2(o[nt][2] * i1, o[nt][3] * i1);
    }
}

// ---------------- launch ----------------
extern "C" void kernel_launch(void* const* d_in, const int* in_sizes, int n_in,
                              void* d_out, int out_size) {
    const float* x      = (const float*)d_in[0];
    const float* mask   = (const float*)d_in[1];
    const float* w_qkv  = (const float*)d_in[2];
    const float* w_qkvm = (const float*)d_in[3];
    const float* w_proj = (const float*)d_in[4];
    const float* b_proj = (const float*)d_in[5];
    const float* rpb    = (const float*)d_in[6];
    const float* posb   = (const float*)d_in[7];
    const int*   relidx = (const int*)  d_in[8];
    float* out = (float*)d_out;

    cudaFuncSetAttribute(gemm_qkv_kernel, cudaFuncAttributeMaxDynamicSharedMemorySize, GEMM_SMEM);
    cudaFuncSetAttribute(gemm_out_kernel, cudaFuncAttributeMaxDynamicSharedMemorySize, GEMM_SMEM);
    cudaFuncSetAttribute(attn_mma,        cudaFuncAttributeMaxDynamicSharedMemorySize, ATT_SMEM);

    preproc_all<<<(NPRE + 255) / 256, 256>>>(mask, relidx, rpb, x, posb, w_qkv, w_qkvm, w_proj);

    gemm_qkv_kernel<<<dim3(QKVC / BN, MROWS / BM, 2), 256, GEMM_SMEM>>>();

    attn_mma<<<dim3(NHEADS, NWIN, 2), 256, ATT_SMEM>>>(mask);

    gemm_out_kernel<<<dim3(DIMC / BN, MROWS / BM), 256, GEMM_SMEM>>>(b_proj, out);
}